// round 10
// baseline (speedup 1.0000x reference)
#include <cuda_runtime.h>
#include <math.h>

// Shapes: B=8, T=2048, S=3, H=12, W_SPLIT=6, L=512, N_NOISE=4, R=4
// x: [8,2048,48], latents_table: [36,18,512], eps_i: [8,2048,(2^(i+2))^2]
// out = concat(lats [8,2048,18,512], noise0..3)

#define B 8
#define T 2048
#define CH 48
#define LDIM 512
#define WTOT 18
#define TC 128
#define NTCH (T / TC)     // 16

// fused grid layout: period-22 interleave of lats (9/period) and noise (13/period)
#define TOTAL_BLOCKS 2816       // 128 periods of 22; lats 1152, noise 1664

__device__ float g_part[B][8][CH];
__device__ float g_mean[B][CH];
__device__ float g_w[B][4][9];
__device__ float g_smu[B][4][T];        // smoothed mu
__device__ float g_wsig[B][4][T][9];    // w_j * sig(refl(t-4+j))

typedef unsigned long long u64;

__device__ __forceinline__ u64 pack_dup(float a) {
    u64 r;
    unsigned int ai = __float_as_uint(a);
    asm("mov.b64 %0, {%1, %2};" : "=l"(r) : "r"(ai), "r"(ai));
    return r;
}
__device__ __forceinline__ u64 pack2(float a, float b) {
    u64 r;
    unsigned int ai = __float_as_uint(a), bi = __float_as_uint(b);
    asm("mov.b64 %0, {%1, %2};" : "=l"(r) : "r"(ai), "r"(bi));
    return r;
}
__device__ __forceinline__ void unpack2(u64 v, float& a, float& b) {
    unsigned int ai, bi;
    asm("mov.b64 {%0, %1}, %2;" : "=r"(ai), "=r"(bi) : "l"(v));
    a = __uint_as_float(ai); b = __uint_as_float(bi);
}
__device__ __forceinline__ void fma2(u64& d, u64 a, u64 b) {
    asm("fma.rn.f32x2 %0, %1, %2, %0;" : "+l"(d) : "l"(a), "l"(b));
}

__device__ __forceinline__ int refl(int t) {
    t = (t < 0) ? -t : t;
    return (t > T - 1) ? (2 * T - 2 - t) : t;
}

// ---------------- stats A: 64-block partial channel sums --------------------
// block = (b, chunk): chunk of 256 t-rows. 384 threads: c=tid%48, r=tid/48.
__global__ __launch_bounds__(384) void statsA_kernel(const float* __restrict__ x) {
    __shared__ float sm[CH * 8];
    int b = blockIdx.x >> 3;
    int chunk = blockIdx.x & 7;
    int tid = threadIdx.x;
    int c = tid % CH, r = tid / CH;     // r in 0..7
    const float* xb = x + ((size_t)b * T + chunk * 256) * CH;
    float s = 0.f;
#pragma unroll 4
    for (int t = r; t < 256; t += 8) s += xb[t * CH + c];
    sm[c * 8 + r] = s;
    __syncthreads();
    if (tid < CH) {
        float tot = 0.f;
#pragma unroll
        for (int rr = 0; rr < 8; rr++) tot += sm[tid * 8 + rr];
        g_part[b][chunk][tid] = tot;
    }
}

// ---------------- stats B: fixed-order reduce + means + weights -------------
__global__ void statsB_kernel() {
    int b = blockIdx.x;
    int tid = threadIdx.x;              // 64 threads
    __shared__ float mean_s[CH];
    if (tid < CH) {
        float tot = 0.f;
#pragma unroll
        for (int k = 0; k < 8; k++) tot += g_part[b][k][tid];
        float m = tot * (1.0f / (float)T);
        g_mean[b][tid] = m;
        mean_s[tid] = m;
    }
    __syncthreads();
    if (tid < 4) {
        float sigma = fmaxf(mean_s[38 + 3 * tid], 0.001f);
        float inv = 0.5f / (sigma * sigma);
        float w[9];
        float sum = 0.f;
#pragma unroll
        for (int j = 0; j < 9; j++) {
            float k = (float)(j - 4);
            w[j] = expf(-k * k * inv);
            sum += w[j];
        }
        float rs = 1.0f / sum;
#pragma unroll
        for (int j = 0; j < 9; j++) g_w[b][tid][j] = w[j] * rs;
    }
}

// ---------------- precompute smoothed mu + per-tap weighted sig -------------
// B*T threads; each handles all 4 noise channels for one (b,t).
__global__ __launch_bounds__(256) void precompute_kernel(const float* __restrict__ x) {
    int idx = blockIdx.x * blockDim.x + threadIdx.x;
    int t = idx & (T - 1);
    int b = idx >> 11;
    const float* xb = x + (size_t)b * T * CH + 36;
    int tj[9];
#pragma unroll
    for (int j = 0; j < 9; j++) tj[j] = refl(t - 4 + j);
#pragma unroll
    for (int ni = 0; ni < 4; ni++) {
        float w[9];
#pragma unroll
        for (int j = 0; j < 9; j++) w[j] = g_w[b][ni][j];
        float smu = 0.f;
        float ws[9];
#pragma unroll
        for (int j = 0; j < 9; j++) {
            float mu = xb[(size_t)tj[j] * CH + 3 * ni];
            float sg = xb[(size_t)tj[j] * CH + 3 * ni + 1];
            smu = fmaf(w[j], mu, smu);
            ws[j] = w[j] * sg;
        }
        g_smu[b][ni][t] = smu;
#pragma unroll
        for (int j = 0; j < 9; j++) g_wsig[b][ni][t][j] = ws[j];
    }
}

// ---------------- lats device path ------------------------------------------
__device__ __forceinline__ void lats_block(
    int lbid, int tid,
    const float* __restrict__ x,
    const float* __restrict__ lt,
    float* __restrict__ out,
    u64 (*env_p)[12])
{
    int wpair = lbid % 9;
    int tc    = (lbid / 9) % NTCH;
    int b     = lbid / (9 * NTCH);
    int half  = tid >> 7;
    int t128  = tid & 127;
    int wgl   = wpair * 2 + half;
    int sec   = wgl / 6;
    int wl    = wgl % 6;
    int t0    = tc * TC;

    for (int i = tid; i < TC * 12; i += 256) {
        int tl = i / 12, h = i - tl * 12;
        float e = x[((size_t)(b * T + t0 + tl)) * CH + sec * 12 + h]
                  - g_mean[b][sec * 12 + h];
        env_p[tl][h] = pack_dup(e);
    }

    const float* latbase = lt + (size_t)(sec * 12) * (WTOT * LDIM)
                              + (size_t)(sec * 6 + wl) * LDIM + t128 * 4;
    u64 latA[12], latB[12];
#pragma unroll
    for (int h = 0; h < 12; h++) {
        float4 v = *(const float4*)(latbase + (size_t)h * WTOT * LDIM);
        latA[h] = pack2(v.x, v.y);
        latB[h] = pack2(v.z, v.w);
    }
    __syncthreads();

    float* outbase = out + (((size_t)(b * T + t0) * WTOT + wgl) * LDIM) + t128 * 4;
#pragma unroll 4
    for (int tl = 0; tl < TC; tl++) {
        u64 accA = 0ull, accB = 0ull;
#pragma unroll
        for (int h = 0; h < 12; h++) {
            u64 e2 = env_p[tl][h];
            fma2(accA, e2, latA[h]);
            fma2(accB, e2, latB[h]);
        }
        float4 o;
        unpack2(accA, o.x, o.y);
        unpack2(accB, o.z, o.w);
        *(float4*)(outbase + (size_t)tl * WTOT * LDIM) = o;
    }
}

// ---------------- noise device path (table-driven) --------------------------
template<int NI, int P4S, int TW>
__device__ __forceinline__ void noise_block(
    int idx,
    const float4* __restrict__ eps,
    float4* __restrict__ out)
{
    const int P4 = 1 << P4S;
    const int NTC = T / TW;
    int pv   = idx & (P4 - 1);
    int rest = idx >> P4S;
    int tc = rest % NTC;
    int b  = rest / NTC;
    if (b >= B) return;
    int t0 = tc * TW;

    const float4* eb = eps + ((size_t)(b * T) << P4S) + pv;
    const float* wsb  = &g_wsig[b][NI][0][0];
    const float* smub = &g_smu[b][NI][0];

    float4 e4[9];
#pragma unroll
    for (int j = 0; j < 9; j++)
        e4[j] = eb[(size_t)refl(t0 - 4 + j) << P4S];

    float4* ob = out + (((size_t)(b * T + t0)) << P4S) + pv;
#pragma unroll
    for (int tt = 0; tt < TW; tt++) {
        int t = t0 + tt;
        const float* ws = wsb + t * 9;      // warp-uniform
        float m = smub[t];
        float4 acc = make_float4(m, m, m, m);
#pragma unroll
        for (int j = 0; j < 9; j++) {
            int s = (tt + j) % 9;           // compile-time after unroll
            float sc = ws[j];
            acc.x = fmaf(sc, e4[s].x, acc.x);
            acc.y = fmaf(sc, e4[s].y, acc.y);
            acc.z = fmaf(sc, e4[s].z, acc.z);
            acc.w = fmaf(sc, e4[s].w, acc.w);
        }
        ob[(size_t)tt << P4S] = acc;
        int tn = refl(t0 + tt + 5);
        e4[tt % 9] = eb[(size_t)tn << P4S];
    }
}

// ---------------- fused mega-kernel -----------------------------------------
__global__ __launch_bounds__(256, 3) void fused_kernel(
    const float* __restrict__ x,
    const float* __restrict__ lt,
    const float4* __restrict__ e0, const float4* __restrict__ e1,
    const float4* __restrict__ e2, const float4* __restrict__ e3,
    float* __restrict__ out)
{
    __shared__ u64 env_p[TC][12];
    int bid = blockIdx.x;
    int p = bid / 22, s = bid - p * 22;
    int tid = threadIdx.x;

    if (s < 9) {
        lats_block(p * 9 + s, tid, x, lt, out, env_p);
        return;
    }
    int nb = p * 13 + (s - 9);      // 0..1663
    const size_t lats_f = (size_t)B * T * WTOT * LDIM;
    if (nb < 1024) {                 // noise3: P4=256, TW=16
        int idx = nb * 256 + tid;
        size_t off = lats_f + (size_t)B * T * (16 + 64 + 256);
        noise_block<3, 8, 16>(idx, e3, (float4*)(out + off));
    } else if (nb < 1280) {          // noise2: P4=64, TW=16
        int idx = (nb - 1024) * 256 + tid;
        size_t off = lats_f + (size_t)B * T * (16 + 64);
        noise_block<2, 6, 16>(idx, e2, (float4*)(out + off));
    } else if (nb < 1536) {          // noise1: P4=16, TW=4
        int idx = (nb - 1280) * 256 + tid;
        size_t off = lats_f + (size_t)B * T * 16;
        noise_block<1, 4, 4>(idx, e1, (float4*)(out + off));
    } else {                         // noise0: P4=4, TW=2
        int idx = (nb - 1536) * 256 + tid;
        noise_block<0, 2, 2>(idx, e0, (float4*)(out + lats_f));
    }
}

extern "C" void kernel_launch(void* const* d_in, const int* in_sizes, int n_in,
                              void* d_out, int out_size)
{
    const float* x  = (const float*)d_in[0];
    const float* lt = (const float*)d_in[1];
    float* out = (float*)d_out;

    statsA_kernel<<<64, 384>>>(x);
    statsB_kernel<<<B, 64>>>();
    precompute_kernel<<<B * T / 256, 256>>>(x);
    fused_kernel<<<TOTAL_BLOCKS, 256>>>(
        x, lt,
        (const float4*)d_in[2], (const float4*)d_in[3],
        (const float4*)d_in[4], (const float4*)d_in[5],
        out);
}

// round 13
// speedup vs baseline: 1.0366x; 1.0366x over previous
#include <cuda_runtime.h>
#include <math.h>

// Shapes: B=8, T=2048, S=3, H=12, W_SPLIT=6, L=512, N_NOISE=4, R=4
// x: [8,2048,48], latents_table: [36,18,512], eps_i: [8,2048,(2^(i+2))^2]
// out = concat(lats [8,2048,18,512], noise0..3)

#define B 8
#define T 2048
#define CH 48
#define LDIM 512
#define WTOT 18
#define TC 128
#define NTCH (T / TC)     // 16

// fused grid layout: period-22 interleave of lats (9/period) and noise (13/period)
#define TOTAL_BLOCKS 2816       // 128 periods of 22; lats 1152, noise 1664

__device__ float g_part[B][8][CH];
__device__ float g_mean[B][CH];
__device__ float g_w[B][4][9];

typedef unsigned long long u64;

__device__ __forceinline__ u64 pack_dup(float a) {
    u64 r;
    unsigned int ai = __float_as_uint(a);
    asm("mov.b64 %0, {%1, %2};" : "=l"(r) : "r"(ai), "r"(ai));
    return r;
}
__device__ __forceinline__ u64 pack2(float a, float b) {
    u64 r;
    unsigned int ai = __float_as_uint(a), bi = __float_as_uint(b);
    asm("mov.b64 %0, {%1, %2};" : "=l"(r) : "r"(ai), "r"(bi));
    return r;
}
__device__ __forceinline__ void unpack2(u64 v, float& a, float& b) {
    unsigned int ai, bi;
    asm("mov.b64 {%0, %1}, %2;" : "=r"(ai), "=r"(bi) : "l"(v));
    a = __uint_as_float(ai); b = __uint_as_float(bi);
}
__device__ __forceinline__ void fma2(u64& d, u64 a, u64 b) {
    asm("fma.rn.f32x2 %0, %1, %2, %0;" : "+l"(d) : "l"(a), "l"(b));
}

// streaming (evict-first) store/load of float4
__device__ __forceinline__ void stcs4(float4* p, float4 v) {
    asm volatile("st.global.cs.v4.f32 [%0], {%1, %2, %3, %4};"
                 :: "l"(p), "f"(v.x), "f"(v.y), "f"(v.z), "f"(v.w) : "memory");
}
__device__ __forceinline__ float4 ldcs4(const float4* p) {
    float4 v;
    asm volatile("ld.global.cs.v4.f32 {%0, %1, %2, %3}, [%4];"
                 : "=f"(v.x), "=f"(v.y), "=f"(v.z), "=f"(v.w) : "l"(p));
    return v;
}

__device__ __forceinline__ int refl(int t) {
    t = (t < 0) ? -t : t;
    return (t > T - 1) ? (2 * T - 2 - t) : t;
}

// ---------------- stats A: 64-block partial channel sums --------------------
__global__ __launch_bounds__(384) void statsA_kernel(const float* __restrict__ x) {
    __shared__ float sm[CH * 8];
    int b = blockIdx.x >> 3;
    int chunk = blockIdx.x & 7;
    int tid = threadIdx.x;
    int c = tid % CH, r = tid / CH;     // r in 0..7
    const float* xb = x + ((size_t)b * T + chunk * 256) * CH;
    float s = 0.f;
#pragma unroll 4
    for (int t = r; t < 256; t += 8) s += xb[t * CH + c];
    sm[c * 8 + r] = s;
    __syncthreads();
    if (tid < CH) {
        float tot = 0.f;
#pragma unroll
        for (int rr = 0; rr < 8; rr++) tot += sm[tid * 8 + rr];
        g_part[b][chunk][tid] = tot;
    }
}

// ---------------- stats B: fixed-order reduce + means + weights -------------
__global__ void statsB_kernel() {
    int b = blockIdx.x;
    int tid = threadIdx.x;              // 64 threads
    __shared__ float mean_s[CH];
    if (tid < CH) {
        float tot = 0.f;
#pragma unroll
        for (int k = 0; k < 8; k++) tot += g_part[b][k][tid];
        float m = tot * (1.0f / (float)T);
        g_mean[b][tid] = m;
        mean_s[tid] = m;
    }
    __syncthreads();
    if (tid < 4) {
        float sigma = fmaxf(mean_s[38 + 3 * tid], 0.001f);
        float inv = 0.5f / (sigma * sigma);
        float w[9];
        float sum = 0.f;
#pragma unroll
        for (int j = 0; j < 9; j++) {
            float k = (float)(j - 4);
            w[j] = expf(-k * k * inv);
            sum += w[j];
        }
        float rs = 1.0f / sum;
#pragma unroll
        for (int j = 0; j < 9; j++) g_w[b][tid][j] = w[j] * rs;
    }
}

// ---------------- lats device path (R8) --------------------------------------
__device__ __forceinline__ void lats_block(
    int lbid, int tid,
    const float* __restrict__ x,
    const float* __restrict__ lt,
    float* __restrict__ out,
    u64 (*env_p)[12])
{
    int wpair = lbid % 9;
    int tc    = (lbid / 9) % NTCH;
    int b     = lbid / (9 * NTCH);
    int half  = tid >> 7;
    int t128  = tid & 127;
    int wgl   = wpair * 2 + half;
    int sec   = wgl / 6;
    int wl    = wgl % 6;
    int t0    = tc * TC;

    for (int i = tid; i < TC * 12; i += 256) {
        int tl = i / 12, h = i - tl * 12;
        float e = x[((size_t)(b * T + t0 + tl)) * CH + sec * 12 + h]
                  - g_mean[b][sec * 12 + h];
        env_p[tl][h] = pack_dup(e);
    }

    const float* latbase = lt + (size_t)(sec * 12) * (WTOT * LDIM)
                              + (size_t)(sec * 6 + wl) * LDIM + t128 * 4;
    u64 latA[12], latB[12];
#pragma unroll
    for (int h = 0; h < 12; h++) {
        float4 v = *(const float4*)(latbase + (size_t)h * WTOT * LDIM);
        latA[h] = pack2(v.x, v.y);
        latB[h] = pack2(v.z, v.w);
    }
    __syncthreads();

    float* outbase = out + (((size_t)(b * T + t0) * WTOT + wgl) * LDIM) + t128 * 4;
#pragma unroll 4
    for (int tl = 0; tl < TC; tl++) {
        u64 accA = 0ull, accB = 0ull;
#pragma unroll
        for (int h = 0; h < 12; h++) {
            u64 e2 = env_p[tl][h];
            fma2(accA, e2, latA[h]);
            fma2(accB, e2, latB[h]);
        }
        float4 o;
        unpack2(accA, o.x, o.y);
        unpack2(accB, o.z, o.w);
        stcs4((float4*)(outbase + (size_t)tl * WTOT * LDIM), o);
    }
}

// ---------------- noise device path (R8: register window) -------------------
template<int NI, int P4S, int TW, bool STREAM_EPS>
__device__ __forceinline__ void noise_block(
    int idx,
    const float* __restrict__ x,
    const float4* __restrict__ eps,
    float4* __restrict__ out)
{
    const int P4 = 1 << P4S;
    const int NTC = T / TW;
    int pv   = idx & (P4 - 1);
    int rest = idx >> P4S;
    int tc = rest % NTC;
    int b  = rest / NTC;
    if (b >= B) return;
    int t0 = tc * TW;

    float w[9];
    const float* wp = g_w[b][NI];
#pragma unroll
    for (int j = 0; j < 9; j++) w[j] = wp[j];

    const float* xb = x + (size_t)b * T * CH + 36 + 3 * NI;
    const float4* eb = eps + ((size_t)(b * T) << P4S) + pv;

    float4 e4[9]; float mm[9], ss[9];
#pragma unroll
    for (int j = 0; j < 9; j++) {
        int tj = refl(t0 - 4 + j);
        e4[j] = STREAM_EPS ? ldcs4(&eb[(size_t)tj << P4S])
                           : eb[(size_t)tj << P4S];
        mm[j] = xb[(size_t)tj * CH];
        ss[j] = xb[(size_t)tj * CH + 1];
    }

    float4* ob = out + (((size_t)(b * T + t0)) << P4S) + pv;
#pragma unroll
    for (int tt = 0; tt < TW; tt++) {
        float accm = 0.f;
        float4 acc = make_float4(0.f, 0.f, 0.f, 0.f);
#pragma unroll
        for (int j = 0; j < 9; j++) {
            int s = (tt + j) % 9;          // compile-time after unroll
            accm = fmaf(w[j], mm[s], accm);
            float sc = w[j] * ss[s];
            acc.x = fmaf(sc, e4[s].x, acc.x);
            acc.y = fmaf(sc, e4[s].y, acc.y);
            acc.z = fmaf(sc, e4[s].z, acc.z);
            acc.w = fmaf(sc, e4[s].w, acc.w);
        }
        stcs4(&ob[(size_t)tt << P4S],
              make_float4(acc.x + accm, acc.y + accm, acc.z + accm, acc.w + accm));
        int tn = refl(t0 + tt + 5);
        int r = tt % 9;
        e4[r] = STREAM_EPS ? ldcs4(&eb[(size_t)tn << P4S])
                           : eb[(size_t)tn << P4S];
        mm[r] = xb[(size_t)tn * CH];
        ss[r] = xb[(size_t)tn * CH + 1];
    }
}

// ---------------- fused mega-kernel (R8 layout) ------------------------------
__global__ __launch_bounds__(256) void fused_kernel(
    const float* __restrict__ x,
    const float* __restrict__ lt,
    const float4* __restrict__ e0, const float4* __restrict__ e1,
    const float4* __restrict__ e2, const float4* __restrict__ e3,
    float* __restrict__ out)
{
    __shared__ u64 env_p[TC][12];
    int bid = blockIdx.x;
    int p = bid / 22, s = bid - p * 22;
    int tid = threadIdx.x;

    if (s < 9) {
        lats_block(p * 9 + s, tid, x, lt, out, env_p);
        return;
    }
    int nb = p * 13 + (s - 9);      // 0..1663
    const size_t lats_f = (size_t)B * T * WTOT * LDIM;
    if (nb < 1024) {                 // noise3: P4=256, TW=16, streaming eps
        int idx = nb * 256 + tid;
        size_t off = lats_f + (size_t)B * T * (16 + 64 + 256);
        noise_block<3, 8, 16, true>(idx, x, e3, (float4*)(out + off));
    } else if (nb < 1280) {          // noise2: P4=64, TW=16
        int idx = (nb - 1024) * 256 + tid;
        size_t off = lats_f + (size_t)B * T * (16 + 64);
        noise_block<2, 6, 16, false>(idx, x, e2, (float4*)(out + off));
    } else if (nb < 1536) {          // noise1: P4=16, TW=4
        int idx = (nb - 1280) * 256 + tid;
        size_t off = lats_f + (size_t)B * T * 16;
        noise_block<1, 4, 4, false>(idx, x, e1, (float4*)(out + off));
    } else {                         // noise0: P4=4, TW=2
        int idx = (nb - 1536) * 256 + tid;
        noise_block<0, 2, 2, false>(idx, x, e0, (float4*)(out + lats_f));
    }
}

extern "C" void kernel_launch(void* const* d_in, const int* in_sizes, int n_in,
                              void* d_out, int out_size)
{
    const float* x  = (const float*)d_in[0];
    const float* lt = (const float*)d_in[1];
    float* out = (float*)d_out;

    statsA_kernel<<<64, 384>>>(x);
    statsB_kernel<<<B, 64>>>();
    fused_kernel<<<TOTAL_BLOCKS, 256>>>(
        x, lt,
        (const float4*)d_in[2], (const float4*)d_in[3],
        (const float4*)d_in[4], (const float4*)d_in[5],
        out);
}

// round 15
// speedup vs baseline: 1.1016x; 1.0627x over previous
#include <cuda_runtime.h>
#include <math.h>

// Shapes: B=8, T=2048, S=3, H=12, W_SPLIT=6, L=512, N_NOISE=4, R=4
// x: [8,2048,48], latents_table: [36,18,512], eps_i: [8,2048,(2^(i+2))^2]
// out = concat(lats [8,2048,18,512], noise0..3)

#define B 8
#define T 2048
#define CH 48
#define LDIM 512
#define WTOT 18
#define TC 128
#define NTCH (T / TC)     // 16
#define NCHK 16           // stats chunks per batch

// fused grid layout: period-22 interleave of lats (9/period) and noise (13/period)
#define TOTAL_BLOCKS 2816       // 128 periods of 22; lats 1152, noise 1664

__device__ float g_part[B][NCHK][CH];   // per-chunk channel sums

typedef unsigned long long u64;

__device__ __forceinline__ u64 pack_dup(float a) {
    u64 r;
    unsigned int ai = __float_as_uint(a);
    asm("mov.b64 %0, {%1, %2};" : "=l"(r) : "r"(ai), "r"(ai));
    return r;
}
__device__ __forceinline__ u64 pack2(float a, float b) {
    u64 r;
    unsigned int ai = __float_as_uint(a), bi = __float_as_uint(b);
    asm("mov.b64 %0, {%1, %2};" : "=l"(r) : "r"(ai), "r"(bi));
    return r;
}
__device__ __forceinline__ void unpack2(u64 v, float& a, float& b) {
    unsigned int ai, bi;
    asm("mov.b64 {%0, %1}, %2;" : "=r"(ai), "=r"(bi) : "l"(v));
    a = __uint_as_float(ai); b = __uint_as_float(bi);
}
__device__ __forceinline__ void fma2(u64& d, u64 a, u64 b) {
    asm("fma.rn.f32x2 %0, %1, %2, %0;" : "+l"(d) : "l"(a), "l"(b));
}

// streaming (evict-first) store/load of float4
__device__ __forceinline__ void stcs4(float4* p, float4 v) {
    asm volatile("st.global.cs.v4.f32 [%0], {%1, %2, %3, %4};"
                 :: "l"(p), "f"(v.x), "f"(v.y), "f"(v.z), "f"(v.w) : "memory");
}
__device__ __forceinline__ float4 ldcs4(const float4* p) {
    float4 v;
    asm volatile("ld.global.cs.v4.f32 {%0, %1, %2, %3}, [%4];"
                 : "=f"(v.x), "=f"(v.y), "=f"(v.z), "=f"(v.w) : "l"(p));
    return v;
}

__device__ __forceinline__ int refl(int t) {
    t = (t < 0) ? -t : t;
    return (t > T - 1) ? (2 * T - 2 - t) : t;
}

// ---------------- stats A: 128-block partial channel sums (float4) ----------
// block = (b, chunk of 128 t-rows). 384 threads: c4=tid%12 (float4 of 48ch),
// r=tid/12 (32 rows in flight). 4 coalesced float4 loads per thread.
__global__ __launch_bounds__(384) void statsA_kernel(const float4* __restrict__ x4) {
    __shared__ float4 sm[32][12];
    int b = blockIdx.x >> 4;
    int chunk = blockIdx.x & (NCHK - 1);
    int tid = threadIdx.x;
    int c4 = tid % 12, r = tid / 12;    // r in 0..31
    const float4* xb = x4 + ((size_t)b * T + chunk * 128) * 12;
    float4 s = make_float4(0.f, 0.f, 0.f, 0.f);
#pragma unroll
    for (int t = 0; t < 128; t += 32) {
        float4 v = xb[(size_t)(t + r) * 12 + c4];
        s.x += v.x; s.y += v.y; s.z += v.z; s.w += v.w;
    }
    sm[r][c4] = s;
    __syncthreads();
    if (tid < 12) {
        float4 tot = make_float4(0.f, 0.f, 0.f, 0.f);
#pragma unroll
        for (int rr = 0; rr < 32; rr++) {
            float4 v = sm[rr][tid];
            tot.x += v.x; tot.y += v.y; tot.z += v.z; tot.w += v.w;
        }
        g_part[b][chunk][tid * 4 + 0] = tot.x;
        g_part[b][chunk][tid * 4 + 1] = tot.y;
        g_part[b][chunk][tid * 4 + 2] = tot.z;
        g_part[b][chunk][tid * 4 + 3] = tot.w;
    }
}

// ---------------- lats device path (R8 core + inline mean reduce) -----------
__device__ __forceinline__ void lats_block(
    int lbid, int tid,
    const float* __restrict__ x,
    const float* __restrict__ lt,
    float* __restrict__ out,
    u64 (*env_p)[12], float* mean_s)
{
    int wpair = lbid % 9;
    int tc    = (lbid / 9) % NTCH;
    int b     = lbid / (9 * NTCH);
    int half  = tid >> 7;
    int t128  = tid & 127;
    int wgl   = wpair * 2 + half;
    int sec   = wgl / 6;            // same for both halves (6 even)
    int wl    = wgl % 6;
    int t0    = tc * TC;

    // per-block fixed-order mean reduce for the 12 channels of this section
    if (tid < 12) {
        float tot = 0.f;
#pragma unroll
        for (int k = 0; k < NCHK; k++) tot += g_part[b][k][sec * 12 + tid];
        mean_s[tid] = tot * (1.0f / (float)T);
    }
    __syncthreads();

    for (int i = tid; i < TC * 12; i += 256) {
        int tl = i / 12, h = i - tl * 12;
        float e = x[((size_t)(b * T + t0 + tl)) * CH + sec * 12 + h] - mean_s[h];
        env_p[tl][h] = pack_dup(e);
    }

    const float* latbase = lt + (size_t)(sec * 12) * (WTOT * LDIM)
                              + (size_t)(sec * 6 + wl) * LDIM + t128 * 4;
    u64 latA[12], latB[12];
#pragma unroll
    for (int h = 0; h < 12; h++) {
        float4 v = *(const float4*)(latbase + (size_t)h * WTOT * LDIM);
        latA[h] = pack2(v.x, v.y);
        latB[h] = pack2(v.z, v.w);
    }
    __syncthreads();

    float* outbase = out + (((size_t)(b * T + t0) * WTOT + wgl) * LDIM) + t128 * 4;
#pragma unroll 4
    for (int tl = 0; tl < TC; tl++) {
        u64 accA = 0ull, accB = 0ull;
#pragma unroll
        for (int h = 0; h < 12; h++) {
            u64 e2 = env_p[tl][h];
            fma2(accA, e2, latA[h]);
            fma2(accB, e2, latB[h]);
        }
        float4 o;
        unpack2(accA, o.x, o.y);
        unpack2(accB, o.z, o.w);
        stcs4((float4*)(outbase + (size_t)tl * WTOT * LDIM), o);
    }
}

// ---------------- noise device path (R8 window + inline weight comp) --------
template<int NI, int P4S, int TW, bool STREAM_EPS>
__device__ __forceinline__ void noise_block(
    int idx,
    const float* __restrict__ x,
    const float4* __restrict__ eps,
    float4* __restrict__ out)
{
    const int P4 = 1 << P4S;
    const int NTC = T / TW;
    int pv   = idx & (P4 - 1);
    int rest = idx >> P4S;
    int tc = rest % NTC;
    int b  = rest / NTC;
    if (b >= B) return;
    int t0 = tc * TW;

    // weights: replicated per thread (uniform loads + expf); identical to
    // the old statsB sequence -> bit-identical results.
    float w[9];
    {
        float tot = 0.f;
#pragma unroll
        for (int k = 0; k < NCHK; k++) tot += g_part[b][k][38 + 3 * NI];
        float sigma = fmaxf(tot * (1.0f / (float)T), 0.001f);
        float inv = 0.5f / (sigma * sigma);
        float sum = 0.f;
#pragma unroll
        for (int j = 0; j < 9; j++) {
            float kk = (float)(j - 4);
            w[j] = expf(-kk * kk * inv);
            sum += w[j];
        }
        float rs = 1.0f / sum;
#pragma unroll
        for (int j = 0; j < 9; j++) w[j] *= rs;
    }

    const float* xb = x + (size_t)b * T * CH + 36 + 3 * NI;
    const float4* eb = eps + ((size_t)(b * T) << P4S) + pv;

    float4 e4[9]; float mm[9], ss[9];
#pragma unroll
    for (int j = 0; j < 9; j++) {
        int tj = refl(t0 - 4 + j);
        e4[j] = STREAM_EPS ? ldcs4(&eb[(size_t)tj << P4S])
                           : eb[(size_t)tj << P4S];
        mm[j] = xb[(size_t)tj * CH];
        ss[j] = xb[(size_t)tj * CH + 1];
    }

    float4* ob = out + (((size_t)(b * T + t0)) << P4S) + pv;
#pragma unroll
    for (int tt = 0; tt < TW; tt++) {
        float accm = 0.f;
        float4 acc = make_float4(0.f, 0.f, 0.f, 0.f);
#pragma unroll
        for (int j = 0; j < 9; j++) {
            int s = (tt + j) % 9;          // compile-time after unroll
            accm = fmaf(w[j], mm[s], accm);
            float sc = w[j] * ss[s];
            acc.x = fmaf(sc, e4[s].x, acc.x);
            acc.y = fmaf(sc, e4[s].y, acc.y);
            acc.z = fmaf(sc, e4[s].z, acc.z);
            acc.w = fmaf(sc, e4[s].w, acc.w);
        }
        stcs4(&ob[(size_t)tt << P4S],
              make_float4(acc.x + accm, acc.y + accm, acc.z + accm, acc.w + accm));
        int tn = refl(t0 + tt + 5);
        int r = tt % 9;
        e4[r] = STREAM_EPS ? ldcs4(&eb[(size_t)tn << P4S])
                           : eb[(size_t)tn << P4S];
        mm[r] = xb[(size_t)tn * CH];
        ss[r] = xb[(size_t)tn * CH + 1];
    }
}

// ---------------- fused mega-kernel (R8 layout) ------------------------------
__global__ __launch_bounds__(256) void fused_kernel(
    const float* __restrict__ x,
    const float* __restrict__ lt,
    const float4* __restrict__ e0, const float4* __restrict__ e1,
    const float4* __restrict__ e2, const float4* __restrict__ e3,
    float* __restrict__ out)
{
    __shared__ u64 env_p[TC][12];
    __shared__ float mean_s[12];
    int bid = blockIdx.x;
    int p = bid / 22, s = bid - p * 22;
    int tid = threadIdx.x;

    if (s < 9) {
        lats_block(p * 9 + s, tid, x, lt, out, env_p, mean_s);
        return;
    }
    int nb = p * 13 + (s - 9);      // 0..1663
    const size_t lats_f = (size_t)B * T * WTOT * LDIM;
    if (nb < 1024) {                 // noise3: P4=256, TW=16, streaming eps
        int idx = nb * 256 + tid;
        size_t off = lats_f + (size_t)B * T * (16 + 64 + 256);
        noise_block<3, 8, 16, true>(idx, x, e3, (float4*)(out + off));
    } else if (nb < 1280) {          // noise2: P4=64, TW=16
        int idx = (nb - 1024) * 256 + tid;
        size_t off = lats_f + (size_t)B * T * (16 + 64);
        noise_block<2, 6, 16, false>(idx, x, e2, (float4*)(out + off));
    } else if (nb < 1536) {          // noise1: P4=16, TW=4
        int idx = (nb - 1280) * 256 + tid;
        size_t off = lats_f + (size_t)B * T * 16;
        noise_block<1, 4, 4, false>(idx, x, e1, (float4*)(out + off));
    } else {                         // noise0: P4=4, TW=2
        int idx = (nb - 1536) * 256 + tid;
        noise_block<0, 2, 2, false>(idx, x, e0, (float4*)(out + lats_f));
    }
}

extern "C" void kernel_launch(void* const* d_in, const int* in_sizes, int n_in,
                              void* d_out, int out_size)
{
    const float* x  = (const float*)d_in[0];
    const float* lt = (const float*)d_in[1];
    float* out = (float*)d_out;

    statsA_kernel<<<B * NCHK, 384>>>((const float4*)x);
    fused_kernel<<<TOTAL_BLOCKS, 256>>>(
        x, lt,
        (const float4*)d_in[2], (const float4*)d_in[3],
        (const float4*)d_in[4], (const float4*)d_in[5],
        out);
}